// round 8
// baseline (speedup 1.0000x reference)
#include <cuda_runtime.h>

#define NN  100000
#define EE  3200000
#define E2  (EE / 2)
#define FIN 256
#define HID 16
#define CC  40
#define NB  592                 // 148 SMs * 4 resident CTAs
#define NTH (NB * 256)          // 151552 threads >= NN (single-pass node indexing)

// ---------------- scratch (device globals; no allocation) ----------------
__device__ int   g_deg4[4 * NN];     // replicated degree counters
__device__ int   g_cur4[4 * NN];     // replicated fill cursors
__device__ float g_dinv[NN];
__device__ int   g_rowptr[NN + 1];   // also used as scan temp
__device__ int   g_col[EE];
__device__ float g_P[NN * HID];      // x@W1 (unscaled, then *= dinv in agg phase 0)
__device__ float g_H[NN * HID];      // dinv-scaled relu hidden
__device__ int   g_bsum[NB];
__device__ int   g_is64;
__device__ unsigned g_cnt = 0;       // global barrier state (monotonic gen)
__device__ unsigned g_gen = 0;

// ---------------- helpers ----------------
__device__ __forceinline__ float4 f4add(float4 a, float4 b) {
    a.x += b.x; a.y += b.y; a.z += b.z; a.w += b.w; return a;
}

// sense-reversing resident-grid barrier (all NB blocks guaranteed co-resident)
__device__ __forceinline__ void gbar() {
    __syncthreads();
    if (threadIdx.x == 0) {
        __threadfence();
        unsigned my = *(volatile unsigned*)&g_gen;
        unsigned t = atomicAdd(&g_cnt, 1);
        if (t == NB - 1) {
            atomicExch(&g_cnt, 0);
            __threadfence();
            atomicAdd(&g_gen, 1);
        } else {
            while (*(volatile unsigned*)&g_gen == my) __nanosleep(32);
        }
        __threadfence();
    }
    __syncthreads();
}

// exclusive scan helper pieces use this smem layout
struct ScanSmem { int ws[8]; };

// ============ Kernel 1: full CSR construction (persistent, 5 barriers) ============
__global__ void __launch_bounds__(256, 4) k_csr(const void* __restrict__ eip) {
    __shared__ int sw[8];
    int b = blockIdx.x, t = threadIdx.x;
    int gt = b * 256 + t;
    int lane = t & 31, warp = t >> 5;

    // ---- phase 0: zero replicated degree counters; detect edge dtype ----
    for (int i = gt; i < 4 * NN; i += NTH) g_deg4[i] = 0;
    if (gt == 0) {
        const int* p = (const int*)eip;
        int z = 0;
        #pragma unroll
        for (int k = 1; k < 64; k += 2) z |= p[k];
        g_is64 = (z == 0) ? 1 : 0;
    }
    gbar();
    int is64 = g_is64;

    // ---- phase 1: degree histogram (2 edges/iter, 4-way replicated) ----
    for (int e2 = gt; e2 < E2; e2 += NTH) {
        int* cnt = &g_deg4[(e2 & 3) * NN];
        int d0, d1;
        if (is64) {
            longlong2 v = ((const longlong2*)((const long long*)eip + EE))[e2];
            d0 = (int)v.x; d1 = (int)v.y;
        } else {
            int2 v = ((const int2*)((const int*)eip + EE))[e2];
            d0 = v.x; d1 = v.y;
        }
        atomicAdd(&cnt[d0], 1);
        atomicAdd(&cnt[d1], 1);
    }
    gbar();

    // ---- phase 2: per-block scan of node degrees (node i == gt, single pass) ----
    int d = 0;
    if (gt < NN)
        d = g_deg4[gt] + g_deg4[NN + gt] + g_deg4[2 * NN + gt] + g_deg4[3 * NN + gt];
    int v = d;
    #pragma unroll
    for (int off = 1; off < 32; off <<= 1) {
        int n = __shfl_up_sync(0xffffffffu, v, off);
        if (lane >= off) v += n;
    }
    if (lane == 31) sw[warp] = v;
    __syncthreads();
    if (t == 0) {
        int r = 0;
        #pragma unroll
        for (int j = 0; j < 8; j++) { int x = sw[j]; sw[j] = r; r += x; }
    }
    __syncthreads();
    int incl = v + sw[warp];
    if (gt < NN) g_rowptr[gt] = incl - d;        // temp: exclusive-in-block
    if (t == 255) g_bsum[b] = incl;              // block total
    gbar();

    // ---- phase 3: block 0 scans the 592 block sums (exclusive, in place) ----
    if (b == 0) {
        int i0 = t * 3;
        int a0 = (i0 + 0 < NB) ? g_bsum[i0 + 0] : 0;
        int a1 = (i0 + 1 < NB) ? g_bsum[i0 + 1] : 0;
        int a2 = (i0 + 2 < NB) ? g_bsum[i0 + 2] : 0;
        int ps = a0 + a1 + a2;
        int w = ps;
        #pragma unroll
        for (int off = 1; off < 32; off <<= 1) {
            int n = __shfl_up_sync(0xffffffffu, w, off);
            if (lane >= off) w += n;
        }
        if (lane == 31) sw[warp] = w;
        __syncthreads();
        if (t == 0) {
            int r = 0;
            #pragma unroll
            for (int j = 0; j < 8; j++) { int x = sw[j]; sw[j] = r; r += x; }
        }
        __syncthreads();
        int ebase = w - ps + sw[warp];
        if (i0 + 0 < NB) g_bsum[i0 + 0] = ebase;
        if (i0 + 1 < NB) g_bsum[i0 + 1] = ebase + a0;
        if (i0 + 2 < NB) g_bsum[i0 + 2] = ebase + a0 + a1;
    }
    gbar();

    // ---- phase 4: finalize rowptr / dinv / replicated cursor bases ----
    if (gt < NN) {
        int s = g_rowptr[gt] + g_bsum[b];
        int d0 = g_deg4[gt],          d1 = g_deg4[NN + gt];
        int d2 = g_deg4[2 * NN + gt], d3 = g_deg4[3 * NN + gt];
        int dt = d0 + d1 + d2 + d3;
        g_rowptr[gt] = s;
        g_dinv[gt]   = rsqrtf((float)dt + 1.0f);     // +1 self-loop
        g_cur4[gt]              = s;
        g_cur4[NN + gt]         = s + d0;
        g_cur4[2 * NN + gt]     = s + d0 + d1;
        g_cur4[3 * NN + gt]     = s + d0 + d1 + d2;
        if (gt == NN - 1) g_rowptr[NN] = s + dt;     // == EE
    }
    gbar();

    // ---- phase 5: CSR fill (2 edges/iter, replica-matched cursors) ----
    for (int e2 = gt; e2 < E2; e2 += NTH) {
        int* cur = &g_cur4[(e2 & 3) * NN];
        int s0, s1, d0, d1;
        if (is64) {
            longlong2 sv = ((const longlong2*)eip)[e2];
            longlong2 dv = ((const longlong2*)((const long long*)eip + EE))[e2];
            s0 = (int)sv.x; s1 = (int)sv.y; d0 = (int)dv.x; d1 = (int)dv.y;
        } else {
            int2 sv = ((const int2*)eip)[e2];
            int2 dv = ((const int2*)((const int*)eip + EE))[e2];
            s0 = sv.x; s1 = sv.y; d0 = dv.x; d1 = dv.y;
        }
        int p0 = atomicAdd(&cur[d0], 1);
        g_col[p0] = s0;
        int p1 = atomicAdd(&cur[d1], 1);
        g_col[p1] = s1;
    }
}

// ============ Kernel 2: GEMM g_P = x @ W1 (forked stream, overlaps k_csr) ============
__global__ void __launch_bounds__(128) k_gemm(const float* __restrict__ x,
                                              const float* __restrict__ W1) {
    __shared__ float xs[32 * 260];     // 260-float pitch: conflict-free float4 LDS
    __shared__ float ws[FIN * HID];
    int tid  = threadIdx.x;
    int base = blockIdx.x * 32;

    float4* ws4 = (float4*)ws;
    const float4* W14 = (const float4*)W1;
    #pragma unroll
    for (int q = tid; q < FIN * HID / 4; q += 128) ws4[q] = W14[q];

    const float4* x4 = (const float4*)x;
    #pragma unroll
    for (int q = tid; q < 32 * 64; q += 128) {
        int r = q >> 6, qi = q & 63;
        *(float4*)&xs[r * 260 + qi * 4] = x4[(size_t)(base + r) * 64 + qi];
    }
    __syncthreads();

    int jg = tid & 3, r = tid >> 2;
    const float4* xr = (const float4*)xs + (size_t)r * 65;
    float4 acc = make_float4(0.f, 0.f, 0.f, 0.f);
    #pragma unroll 4
    for (int k4 = 0; k4 < 64; k4++) {
        float4 xv = xr[k4];
        float4 w0 = ws4[(k4 * 4 + 0) * 4 + jg];
        float4 w1 = ws4[(k4 * 4 + 1) * 4 + jg];
        float4 w2 = ws4[(k4 * 4 + 2) * 4 + jg];
        float4 w3 = ws4[(k4 * 4 + 3) * 4 + jg];
        acc.x += xv.x * w0.x + xv.y * w1.x + xv.z * w2.x + xv.w * w3.x;
        acc.y += xv.x * w0.y + xv.y * w1.y + xv.z * w2.y + xv.w * w3.y;
        acc.z += xv.x * w0.z + xv.y * w1.z + xv.z * w2.z + xv.w * w3.z;
        acc.w += xv.x * w0.w + xv.y * w1.w + xv.z * w2.w + xv.w * w3.w;
    }
    int row = base + r;           // grid exact: 3125*32 == NN
    ((float4*)g_P)[(size_t)row * 4 + jg] = acc;
}

// ============ Kernel 3: scaleP + agg1 + agg2/final (persistent, 2 barriers) ============
__global__ void __launch_bounds__(256, 4) k_agg_all(const float* __restrict__ b1,
                                                    const float* __restrict__ W2,
                                                    const float* __restrict__ b2,
                                                    float* __restrict__ out) {
    __shared__ float w2s[HID * CC];
    __shared__ float b2s[CC];
    __shared__ float gsm[8][16];
    int b = blockIdx.x, t = threadIdx.x;
    int gt = b * 256 + t;
    int lane = t & 31, warp = t >> 5;
    int el = lane >> 2, c = lane & 3;

    for (int q = t; q < HID * CC; q += 256) w2s[q] = W2[q];
    if (t < CC) b2s[t] = b2[t];

    // ---- phase 0: P *= dinv (row broadcast) ----
    for (int q = gt; q < NN * 4; q += NTH) {
        float di = g_dinv[q >> 2];
        float4 v = ((float4*)g_P)[q];
        v.x *= di; v.y *= di; v.z *= di; v.w *= di;
        ((float4*)g_P)[q] = v;
    }
    gbar();

    // ---- phase 1: layer-1 aggregation, warp-per-node ----
    {
        const float4* in4 = (const float4*)g_P;
        float4*      out4 = (float4*)g_H;
        int gw = b * 8 + warp;             // 4736 warps total
        for (int i = gw; i < NN; i += NB * 8) {
            int e0 = g_rowptr[i], e1 = g_rowptr[i + 1];
            float4 acc = make_float4(0.f, 0.f, 0.f, 0.f);
            for (int e = e0 + el; e < e1; e += 8) {
                int s = g_col[e];
                acc = f4add(acc, in4[(size_t)s * 4 + c]);
            }
            #pragma unroll
            for (int off = 16; off >= 4; off >>= 1) {
                acc.x += __shfl_down_sync(0xffffffffu, acc.x, off);
                acc.y += __shfl_down_sync(0xffffffffu, acc.y, off);
                acc.z += __shfl_down_sync(0xffffffffu, acc.z, off);
                acc.w += __shfl_down_sync(0xffffffffu, acc.w, off);
            }
            if (el == 0) {
                acc = f4add(acc, in4[(size_t)i * 4 + c]);   // self-loop (pre-scaled)
                float di = g_dinv[i];
                float4 bb = ((const float4*)b1)[c];
                float4 v;
                v.x = fmaxf(acc.x * di + bb.x, 0.f) * di;
                v.y = fmaxf(acc.y * di + bb.y, 0.f) * di;
                v.z = fmaxf(acc.z * di + bb.z, 0.f) * di;
                v.w = fmaxf(acc.w * di + bb.w, 0.f) * di;
                out4[(size_t)i * 4 + c] = v;
            }
        }
    }
    gbar();

    // ---- phase 2: layer-2 aggregation + W2 + bias + log_softmax + store ----
    {
        const float4* in4 = (const float4*)g_H;
        int gw = b * 8 + warp;
        for (int i = gw; i < NN; i += NB * 8) {
            int e0 = g_rowptr[i], e1 = g_rowptr[i + 1];
            float4 acc = make_float4(0.f, 0.f, 0.f, 0.f);
            for (int e = e0 + el; e < e1; e += 8) {
                int s = g_col[e];
                acc = f4add(acc, in4[(size_t)s * 4 + c]);
            }
            #pragma unroll
            for (int off = 16; off >= 4; off >>= 1) {
                acc.x += __shfl_down_sync(0xffffffffu, acc.x, off);
                acc.y += __shfl_down_sync(0xffffffffu, acc.y, off);
                acc.z += __shfl_down_sync(0xffffffffu, acc.z, off);
                acc.w += __shfl_down_sync(0xffffffffu, acc.w, off);
            }
            if (el == 0) {
                acc = f4add(acc, in4[(size_t)i * 4 + c]);
                float di = g_dinv[i];
                gsm[warp][c * 4 + 0] = acc.x * di;
                gsm[warp][c * 4 + 1] = acc.y * di;
                gsm[warp][c * 4 + 2] = acc.z * di;
                gsm[warp][c * 4 + 3] = acc.w * di;
            }
            __syncwarp();

            float g[HID];
            #pragma unroll
            for (int f = 0; f < HID; f++) g[f] = gsm[warp][f];
            __syncwarp();

            float a0 = b2s[lane];
            #pragma unroll
            for (int f = 0; f < HID; f++) a0 += g[f] * w2s[f * CC + lane];
            float a1 = -1e30f;
            if (lane < 8) {
                a1 = b2s[lane + 32];
                #pragma unroll
                for (int f = 0; f < HID; f++) a1 += g[f] * w2s[f * CC + lane + 32];
            }

            float m = fmaxf(a0, a1);
            #pragma unroll
            for (int off = 16; off >= 1; off >>= 1)
                m = fmaxf(m, __shfl_xor_sync(0xffffffffu, m, off));
            float s = __expf(a0 - m) + ((lane < 8) ? __expf(a1 - m) : 0.f);
            #pragma unroll
            for (int off = 16; off >= 1; off >>= 1)
                s += __shfl_xor_sync(0xffffffffu, s, off);
            float lse = m + __logf(s);

            out[(size_t)i * CC + lane] = a0 - lse;
            if (lane < 8) out[(size_t)i * CC + lane + 32] = a1 - lse;
        }
    }
}

// ---------------- launch ----------------
extern "C" void kernel_launch(void* const* d_in, const int* in_sizes, int n_in,
                              void* d_out, int out_size) {
    const float* x  = (const float*)d_in[0];
    const void*  ei = (const void*)d_in[1];   // int64 or int32, detected on device
    const float* W1 = (const float*)d_in[2];
    const float* b1 = (const float*)d_in[3];
    const float* W2 = (const float*)d_in[4];
    const float* b2 = (const float*)d_in[5];
    float* out = (float*)d_out;

    // lazily created once (outside capture, during the correctness run)
    static cudaStream_t s2 = nullptr;
    static cudaEvent_t ev_fork = nullptr, ev_gemm = nullptr;
    if (!s2) {
        cudaStreamCreateWithFlags(&s2, cudaStreamNonBlocking);
        cudaEventCreateWithFlags(&ev_fork, cudaEventDisableTiming);
        cudaEventCreateWithFlags(&ev_gemm, cudaEventDisableTiming);
    }

    // fork: gemm branch overlaps the entire CSR construction
    cudaEventRecord(ev_fork, 0);
    cudaStreamWaitEvent(s2, ev_fork, 0);
    k_gemm<<<NN / 32, 128, 0, s2>>>(x, W1);
    cudaEventRecord(ev_gemm, s2);

    // main branch: persistent CSR construction (init+deg+scan+fill, 5 gbar)
    k_csr<<<NB, 256>>>(ei);

    // join, then persistent scaleP+agg1+agg2/final (2 gbar)
    cudaStreamWaitEvent(0, ev_gemm, 0);
    k_agg_all<<<NB, 256>>>(b1, W2, b2, out);
}

// round 10
// speedup vs baseline: 1.8940x; 1.8940x over previous
#include <cuda_runtime.h>

#define NN  100000
#define EE  3200000
#define FIN 256
#define HID 16
#define CC  40
#define NB_SCAN 98   // ceil(100000/1024)

// ---------------- scratch (device globals; no allocation) ----------------
__device__ int   g_deg[NN];
__device__ float g_dinv[NN];
__device__ int   g_rowptr[NN + 1];
__device__ int   g_cursor[NN];
__device__ int   g_col[EE];
__device__ float g_P[NN * HID];   // x@W1 (unscaled, then *= dinv in k_scaleP)
__device__ float g_H[NN * HID];   // dinv-scaled relu hidden
__device__ int   g_bsum[NB_SCAN];
__device__ int   g_is64;

// ---------------- helpers ----------------
__device__ __forceinline__ float4 f4add(float4 a, float4 b) {
    a.x += b.x; a.y += b.y; a.z += b.z; a.w += b.w; return a;
}

// ---------------- init: zero degrees + edge dtype detection ----------------
// int64 little-endian nonneg values < 2^31 => every odd 32-bit word is 0.
__global__ void k_init(const int* __restrict__ p) {
    int i = blockIdx.x * blockDim.x + threadIdx.x;
    if (i < NN) g_deg[i] = 0;
    if (i == 0) {
        int z = 0;
        #pragma unroll
        for (int k = 1; k < 64; k += 2) z |= p[k];
        g_is64 = (z == 0) ? 1 : 0;
    }
}

// ---------------- degree count: 2 edges per thread, vector loads ----------------
__global__ void k_deg(const void* __restrict__ eip) {
    int t = blockIdx.x * blockDim.x + threadIdx.x;   // t < EE/2
    if (t >= EE / 2) return;
    if (g_is64) {
        longlong2 v = ((const longlong2*)((const long long*)eip + EE))[t];
        atomicAdd(&g_deg[(int)v.x], 1);
        atomicAdd(&g_deg[(int)v.y], 1);
    } else {
        int2 v = ((const int2*)((const int*)eip + EE))[t];
        atomicAdd(&g_deg[v.x], 1);
        atomicAdd(&g_deg[v.y], 1);
    }
}

// ---------------- block scan (warp-shuffle based) ----------------
// writes block-exclusive prefix into g_cursor, block total into g_bsum
__global__ void __launch_bounds__(1024) k_scan1() {
    __shared__ int wsum[32];
    int t = threadIdx.x;
    int i = blockIdx.x * 1024 + t;
    int d = (i < NN) ? g_deg[i] : 0;
    int v = d;
    #pragma unroll
    for (int off = 1; off < 32; off <<= 1) {
        int n = __shfl_up_sync(0xffffffffu, v, off);
        if ((t & 31) >= off) v += n;
    }
    if ((t & 31) == 31) wsum[t >> 5] = v;
    __syncthreads();
    if (t < 32) {
        int w = wsum[t];
        #pragma unroll
        for (int off = 1; off < 32; off <<= 1) {
            int n = __shfl_up_sync(0xffffffffu, w, off);
            if (t >= off) w += n;
        }
        wsum[t] = w;
    }
    __syncthreads();
    int base = (t >= 32) ? wsum[(t >> 5) - 1] : 0;
    int incl = v + base;
    if (i < NN) g_cursor[i] = incl - d;
    if (t == 1023) g_bsum[blockIdx.x] = incl;
}

// ---------------- scan of the 98 block sums (in place -> exclusive) ----------------
__global__ void __launch_bounds__(128) k_scan2() {
    __shared__ int ws[4];
    int t = threadIdx.x, lane = t & 31, w = t >> 5;
    int d = (t < NB_SCAN) ? g_bsum[t] : 0;
    int v = d;
    #pragma unroll
    for (int off = 1; off < 32; off <<= 1) {
        int n = __shfl_up_sync(0xffffffffu, v, off);
        if (lane >= off) v += n;
    }
    if (lane == 31) ws[w] = v;
    __syncthreads();
    if (t == 0) {
        int r = 0;
        #pragma unroll
        for (int j = 0; j < 4; j++) { int x = ws[j]; ws[j] = r; r += x; }
    }
    __syncthreads();
    v += ws[w];
    if (t < NB_SCAN) g_bsum[t] = v - d;   // exclusive prefix
}

// ---------------- scan finalize: rowptr, cursor, dinv ----------------
__global__ void __launch_bounds__(512) k_scan3() {
    int i = blockIdx.x * 512 + threadIdx.x;
    if (i < NN) {
        int s = g_cursor[i] + g_bsum[i >> 10];
        g_rowptr[i] = s;
        g_cursor[i] = s;
        g_dinv[i]   = rsqrtf((float)g_deg[i] + 1.0f);  // +1 self-loop
        if (i == NN - 1) g_rowptr[NN] = s + g_deg[i];  // == EE
    }
}

// ---------------- CSR fill: 2 edges per thread, vector loads ----------------
__global__ void k_fill(const void* __restrict__ eip) {
    int t = blockIdx.x * blockDim.x + threadIdx.x;   // t < EE/2
    if (t >= EE / 2) return;
    if (g_is64) {
        longlong2 s = ((const longlong2*)eip)[t];
        longlong2 d = ((const longlong2*)((const long long*)eip + EE))[t];
        int p0 = atomicAdd(&g_cursor[(int)d.x], 1);
        g_col[p0] = (int)s.x;
        int p1 = atomicAdd(&g_cursor[(int)d.y], 1);
        g_col[p1] = (int)s.y;
    } else {
        int2 s = ((const int2*)eip)[t];
        int2 d = ((const int2*)((const int*)eip + EE))[t];
        int p0 = atomicAdd(&g_cursor[d.x], 1);
        g_col[p0] = s.x;
        int p1 = atomicAdd(&g_cursor[d.y], 1);
        g_col[p1] = s.y;
    }
}

// ---------------- GEMM: g_P = x @ W1 (unscaled), [N,16] ----------------
// LDS-economy version: 128 rows/block, K chunked by 64, 4 rows x 4 cols per
// thread. Row assignment strided by 32 so the 8 row-groups of a warp map to 8
// distinct bank-quads (pitch 17 float4) -> every x LDS.128 has 8 unique 16B
// addresses = 128B = 1 wavefront. W loads are 4-way broadcast.
#define RB 128          // rows per block
#define KC 64           // k-chunk
#define XP 17           // xs pitch in float4 units (16 data + 1 pad)
__global__ void __launch_bounds__(128) k_gemm(const float* __restrict__ x,
                                              const float* __restrict__ W1) {
    __shared__ float4 xs[RB * XP];           // 34816 B
    __shared__ float4 ws[KC * HID / 4];      // 4096 B
    int tid = threadIdx.x;
    int rg = tid >> 2, jg = tid & 3;         // rg in [0,32), jg in [0,4)
    int base = blockIdx.x * RB;

    float4 acc[4];
    #pragma unroll
    for (int r = 0; r < 4; r++) acc[r] = make_float4(0.f, 0.f, 0.f, 0.f);

    const float4* x4 = (const float4*)x;
    const float4* W4 = (const float4*)W1;

    for (int c = 0; c < FIN / KC; c++) {
        // stage W chunk: k rows c*KC..+KC, all 16 cols (row-major [FIN][HID])
        #pragma unroll
        for (int q = tid; q < KC * HID / 4; q += 128)
            ws[q] = W4[c * (KC * HID / 4) + q];
        // stage x chunk: 128 rows x 16 float4 (coalesced), zero-pad OOB rows
        #pragma unroll
        for (int q = tid; q < RB * (KC / 4); q += 128) {
            int row = q >> 4, f4i = q & 15;
            int grow = base + row;
            float4 v = make_float4(0.f, 0.f, 0.f, 0.f);
            if (grow < NN) v = x4[(size_t)grow * (FIN / 4) + c * (KC / 4) + f4i];
            xs[row * XP + f4i] = v;
        }
        __syncthreads();

        #pragma unroll
        for (int k4 = 0; k4 < KC / 4; k4++) {
            float4 w0 = ws[(k4 * 4 + 0) * 4 + jg];
            float4 w1 = ws[(k4 * 4 + 1) * 4 + jg];
            float4 w2 = ws[(k4 * 4 + 2) * 4 + jg];
            float4 w3 = ws[(k4 * 4 + 3) * 4 + jg];
            #pragma unroll
            for (int r = 0; r < 4; r++) {
                float4 xv = xs[(rg + 32 * r) * XP + k4];
                acc[r].x += xv.x * w0.x + xv.y * w1.x + xv.z * w2.x + xv.w * w3.x;
                acc[r].y += xv.x * w0.y + xv.y * w1.y + xv.z * w2.y + xv.w * w3.y;
                acc[r].z += xv.x * w0.z + xv.y * w1.z + xv.z * w2.z + xv.w * w3.z;
                acc[r].w += xv.x * w0.w + xv.y * w1.w + xv.z * w2.w + xv.w * w3.w;
            }
        }
        __syncthreads();
    }

    #pragma unroll
    for (int r = 0; r < 4; r++) {
        int row = base + rg + 32 * r;
        if (row < NN) ((float4*)g_P)[(size_t)row * 4 + jg] = acc[r];
    }
}

// ---------------- P *= dinv (row broadcast); overlaps k_fill ----------------
__global__ void __launch_bounds__(512) k_scaleP() {
    int t = blockIdx.x * 512 + threadIdx.x;   // t < NN*4 (float4 index)
    if (t < NN * 4) {
        float di = g_dinv[t >> 2];
        float4 v = ((float4*)g_P)[t];
        v.x *= di; v.y *= di; v.z *= di; v.w *= di;
        ((float4*)g_P)[t] = v;
    }
}

// ---------------- Layer-1 aggregation (warp-per-node) ----------------
// H' = dinv * relu(dinv*(sum P'[col] + P'[i]) + b1)   (P' pre-scaled by dinv)
__global__ void __launch_bounds__(256) k_agg1(const float* __restrict__ bias) {
    const float4* in4 = (const float4*)g_P;
    float4*      out4 = (float4*)g_H;
    int warp = threadIdx.x >> 5;
    int lane = threadIdx.x & 31;
    int el = lane >> 2, c = lane & 3;
    int i = blockIdx.x * 8 + warp;        // grid exact: 12500*8 == NN

    int e0 = g_rowptr[i];
    int e1 = g_rowptr[i + 1];
    float4 acc = make_float4(0.f, 0.f, 0.f, 0.f);
    for (int e = e0 + el; e < e1; e += 8) {
        int s = g_col[e];
        acc = f4add(acc, in4[(size_t)s * 4 + c]);
    }
    #pragma unroll
    for (int off = 16; off >= 4; off >>= 1) {
        acc.x += __shfl_down_sync(0xffffffffu, acc.x, off);
        acc.y += __shfl_down_sync(0xffffffffu, acc.y, off);
        acc.z += __shfl_down_sync(0xffffffffu, acc.z, off);
        acc.w += __shfl_down_sync(0xffffffffu, acc.w, off);
    }
    if (el == 0) {
        acc = f4add(acc, in4[(size_t)i * 4 + c]);   // self-loop (pre-scaled)
        float di = g_dinv[i];
        float4 b = ((const float4*)bias)[c];
        float4 v;
        v.x = fmaxf(acc.x * di + b.x, 0.f) * di;
        v.y = fmaxf(acc.y * di + b.y, 0.f) * di;
        v.z = fmaxf(acc.z * di + b.z, 0.f) * di;
        v.w = fmaxf(acc.w * di + b.w, 0.f) * di;
        out4[(size_t)i * 4 + c] = v;
    }
}

// ---------------- Fused layer-2 agg + W2 + bias + log_softmax + store ----------------
__global__ void __launch_bounds__(256) k_agg2_final(const float* __restrict__ W2,
                                                    const float* __restrict__ b2,
                                                    float* __restrict__ out) {
    __shared__ float w2s[HID * CC];
    __shared__ float b2s[CC];
    __shared__ float gsm[8][16];
    int tid = threadIdx.x;
    for (int q = tid; q < HID * CC; q += 256) w2s[q] = W2[q];
    if (tid < CC) b2s[tid] = b2[tid];
    __syncthreads();

    int warp = tid >> 5, lane = tid & 31;
    int el = lane >> 2, c = lane & 3;
    int i = blockIdx.x * 8 + warp;        // grid exact

    const float4* in4 = (const float4*)g_H;
    int e0 = g_rowptr[i];
    int e1 = g_rowptr[i + 1];
    float4 acc = make_float4(0.f, 0.f, 0.f, 0.f);
    for (int e = e0 + el; e < e1; e += 8) {
        int s = g_col[e];
        acc = f4add(acc, in4[(size_t)s * 4 + c]);
    }
    #pragma unroll
    for (int off = 16; off >= 4; off >>= 1) {
        acc.x += __shfl_down_sync(0xffffffffu, acc.x, off);
        acc.y += __shfl_down_sync(0xffffffffu, acc.y, off);
        acc.z += __shfl_down_sync(0xffffffffu, acc.z, off);
        acc.w += __shfl_down_sync(0xffffffffu, acc.w, off);
    }
    if (el == 0) {
        acc = f4add(acc, in4[(size_t)i * 4 + c]);
        float di = g_dinv[i];
        gsm[warp][c * 4 + 0] = acc.x * di;
        gsm[warp][c * 4 + 1] = acc.y * di;
        gsm[warp][c * 4 + 2] = acc.z * di;
        gsm[warp][c * 4 + 3] = acc.w * di;
    }
    __syncwarp();

    float g[HID];
    #pragma unroll
    for (int f = 0; f < HID; f++) g[f] = gsm[warp][f];

    float a0 = b2s[lane];
    #pragma unroll
    for (int f = 0; f < HID; f++) a0 += g[f] * w2s[f * CC + lane];
    float a1 = -1e30f;
    if (lane < 8) {
        a1 = b2s[lane + 32];
        #pragma unroll
        for (int f = 0; f < HID; f++) a1 += g[f] * w2s[f * CC + lane + 32];
    }

    float m = fmaxf(a0, a1);
    #pragma unroll
    for (int off = 16; off >= 1; off >>= 1)
        m = fmaxf(m, __shfl_xor_sync(0xffffffffu, m, off));
    float s = __expf(a0 - m) + ((lane < 8) ? __expf(a1 - m) : 0.f);
    #pragma unroll
    for (int off = 16; off >= 1; off >>= 1)
        s += __shfl_xor_sync(0xffffffffu, s, off);
    float lse = m + __logf(s);

    out[(size_t)i * CC + lane] = a0 - lse;
    if (lane < 8) out[(size_t)i * CC + lane + 32] = a1 - lse;
}

// ---------------- launch ----------------
extern "C" void kernel_launch(void* const* d_in, const int* in_sizes, int n_in,
                              void* d_out, int out_size) {
    const float* x  = (const float*)d_in[0];
    const void*  ei = (const void*)d_in[1];   // int64 or int32, detected on device
    const float* W1 = (const float*)d_in[2];
    const float* b1 = (const float*)d_in[3];
    const float* W2 = (const float*)d_in[4];
    const float* b2 = (const float*)d_in[5];
    float* out = (float*)d_out;

    // lazily created once (outside capture, during the correctness run)
    static cudaStream_t s2 = nullptr;
    static cudaEvent_t ev_fork = nullptr, ev_scan3 = nullptr, ev_scaled = nullptr;
    if (!s2) {
        cudaStreamCreateWithFlags(&s2, cudaStreamNonBlocking);
        cudaEventCreateWithFlags(&ev_fork,   cudaEventDisableTiming);
        cudaEventCreateWithFlags(&ev_scan3,  cudaEventDisableTiming);
        cudaEventCreateWithFlags(&ev_scaled, cudaEventDisableTiming);
    }

    // fork: gemm branch (independent of edge processing)
    cudaEventRecord(ev_fork, 0);
    cudaStreamWaitEvent(s2, ev_fork, 0);
    k_gemm<<<(NN + RB - 1) / RB, 128, 0, s2>>>(x, W1);

    // main branch: CSR construction
    k_init<<<(NN + 511) / 512, 512>>>((const int*)ei);
    k_deg<<<(EE / 2 + 255) / 256, 256>>>(ei);
    k_scan1<<<NB_SCAN, 1024>>>();
    k_scan2<<<1, 128>>>();
    k_scan3<<<(NN + 511) / 512, 512>>>();
    cudaEventRecord(ev_scan3, 0);
    k_fill<<<(EE / 2 + 255) / 256, 256>>>(ei);

    // scaleP on gemm branch (needs gemm + scan3), overlaps k_fill
    cudaStreamWaitEvent(s2, ev_scan3, 0);
    k_scaleP<<<(NN * 4 + 511) / 512, 512, 0, s2>>>();
    cudaEventRecord(ev_scaled, s2);
    cudaStreamWaitEvent(0, ev_scaled, 0);

    // join: aggregations
    k_agg1<<<NN / 8, 256>>>(b1);
    k_agg2_final<<<NN / 8, 256>>>(W2, b2, out);
}